// round 1
// baseline (speedup 1.0000x reference)
#include <cuda_runtime.h>
#include <math.h>

#define NB 16
#define NC 256
#define NE 9216
#define KSEL 4096

// Scratch (no allocations allowed) — device globals.
__device__ float g_score[NB * NE];
__device__ int   g_keep[NB * KSEL];

// ---------------------------------------------------------------------------
// Kernel 1: score[b,e] = sum_c x[b,c,e]^2
// grid = (NE/256, NB), block = 256. Coalesced across e; 256-deep c loop.
// ---------------------------------------------------------------------------
__global__ void score_kernel(const float* __restrict__ x) {
    int e = blockIdx.x * blockDim.x + threadIdx.x;
    int b = blockIdx.y;
    const float* xb = x + (size_t)b * NC * NE + e;
    float acc = 0.f;
#pragma unroll 16
    for (int c = 0; c < NC; ++c) {
        float v = __ldg(xb + (size_t)c * NE);
        acc = fmaf(v, v, acc);
    }
    g_score[b * NE + e] = acc;
}

// ---------------------------------------------------------------------------
// Block exclusive scan over 1024 threads (32 warps). wsum is shared[32].
// ---------------------------------------------------------------------------
__device__ __forceinline__ int block_exscan(int val, int t, int* wsum) {
    int lane = t & 31, w = t >> 5;
    int x = val;
#pragma unroll
    for (int d = 1; d < 32; d <<= 1) {
        int y = __shfl_up_sync(0xFFFFFFFFu, x, d);
        if (lane >= d) x += y;
    }
    __syncthreads();               // protect wsum reuse across calls
    if (lane == 31) wsum[w] = x;   // inclusive warp total
    __syncthreads();
    if (w == 0) {
        int s = wsum[lane];
        int xs = s;
#pragma unroll
        for (int d = 1; d < 32; d <<= 1) {
            int y = __shfl_up_sync(0xFFFFFFFFu, xs, d);
            if (lane >= d) xs += y;
        }
        wsum[lane] = xs - s;       // exclusive warp offsets
    }
    __syncthreads();
    return wsum[w] + x - val;      // exclusive for this thread
}

// ---------------------------------------------------------------------------
// Kernel 2: per-mesh K-th-largest threshold (MSD radix select on order-
// transformed float bits) + stable tie-break by ascending index + compaction.
// One CTA of 1024 threads per mesh.
// ---------------------------------------------------------------------------
__global__ __launch_bounds__(1024) void select_kernel(const void* __restrict__ ec_raw) {
    __shared__ unsigned int skey[NE];      // 36 KB
    __shared__ unsigned int hist[256];
    __shared__ unsigned int bcast[2];
    __shared__ int wsum[32];

    const int t = threadIdx.x;
    const int b = blockIdx.x;

    // edges_count dtype robustness: int64 vs int32 (jax x64 demotion).
    // Counts are always >= 8704, never 0, so ec32[1]==0 <=> int64 layout.
    const int* ec32 = (const int*)ec_raw;
    long long cnt;
    if (ec32[1] == 0) cnt = ((const long long*)ec_raw)[b];
    else              cnt = (long long)ec32[b];

    // Load order-transformed keys (monotone float->uint; invalid edges -> 0,
    // below any valid non-negative score which maps to >= 0x80000000).
    for (int e = t; e < NE; e += 1024) {
        unsigned int bits = 0u;
        if (e < cnt) {
            bits = __float_as_uint(g_score[b * NE + e]);
            bits = (bits & 0x80000000u) ? ~bits : (bits | 0x80000000u);
        }
        skey[e] = bits;
    }
    __syncthreads();

    // 4-pass MSD radix select for the KSEL-th largest key.
    unsigned int prefix = 0, pmask = 0;
    int kth = KSEL;
    for (int shift = 24; shift >= 0; shift -= 8) {
        if (t < 256) hist[t] = 0;
        __syncthreads();
        for (int e = t; e < NE; e += 1024) {
            unsigned int key = skey[e];
            if ((key & pmask) == prefix)
                atomicAdd(&hist[(key >> shift) & 255u], 1u);
        }
        __syncthreads();
        if (t == 0) {
            unsigned int cum = 0; int v = 255;
            for (; v > 0; --v) { cum += hist[v]; if ((int)cum >= kth) break; }
            if ((int)cum < kth) cum += hist[0];  // v==0 fallthrough
            bcast[0] = (unsigned int)v;
            bcast[1] = (unsigned int)(kth - (int)(cum - hist[v]));
        }
        __syncthreads();
        prefix |= bcast[0] << shift;
        pmask  |= 0xFFu << shift;
        kth = (int)bcast[1];
        __syncthreads();
    }

    const unsigned int T = prefix;   // key of the KSEL-th largest element
    const int needed_eq = kth;       // # of ==T elements to keep (lowest idx first)

    // Per-thread contiguous chunk of 9 elements (1024 * 9 = 9216).
    const int base = t * 9;
    unsigned int keys[9];
#pragma unroll
    for (int i = 0; i < 9; ++i) keys[i] = skey[base + i];

    // Pass A: rank among ==T elements (index order).
    int eqpre[9]; int eqcnt = 0;
#pragma unroll
    for (int i = 0; i < 9; ++i) { eqpre[i] = eqcnt; eqcnt += (keys[i] == T); }
    int eqoff = block_exscan(eqcnt, t, wsum);

    // Pass B: keep-flag compaction (ascending index -> ascending output).
    int kpre[9]; int kcnt = 0;
#pragma unroll
    for (int i = 0; i < 9; ++i) {
        bool keep = (keys[i] > T) || (keys[i] == T && (eqoff + eqpre[i]) < needed_eq);
        kpre[i] = kcnt; kcnt += keep;
    }
    int koff = block_exscan(kcnt, t, wsum);
#pragma unroll
    for (int i = 0; i < 9; ++i) {
        bool keep = (keys[i] > T) || (keys[i] == T && (eqoff + eqpre[i]) < needed_eq);
        if (keep) g_keep[b * KSEL + koff + kpre[i]] = base + i;
    }
}

// ---------------------------------------------------------------------------
// Kernel 3: gather out[b,c,k] = x[b,c,keep[b,k]].
// Each block: one (b, c-group-of-8, k-block-of-256). Thread loads its keep
// index once, then serves 8 channel rows (8 independent loads -> MLP 8).
// ---------------------------------------------------------------------------
__global__ void gather_kernel(const float* __restrict__ x, float* __restrict__ out) {
    const int KBLK = KSEL / 256;           // 16
    int kblk = blockIdx.x % KBLK;
    int c8   = (blockIdx.x / KBLK) % (NC / 8);
    int b    = blockIdx.x / (KBLK * (NC / 8));
    int k = kblk * 256 + threadIdx.x;
    int e = g_keep[b * KSEL + k];
    size_t row = (size_t)b * NC + (size_t)c8 * 8;
    const float* xp = x + row * NE + e;
    float* op = out + row * KSEL + k;
#pragma unroll
    for (int j = 0; j < 8; ++j)
        op[(size_t)j * KSEL] = __ldg(xp + (size_t)j * NE);
}

// ---------------------------------------------------------------------------
extern "C" void kernel_launch(void* const* d_in, const int* in_sizes, int n_in,
                              void* d_out, int out_size) {
    const float* x = (const float*)d_in[0];
    const void* ec = d_in[1];     // edges_count (int64 or int32; detected on device)
    float* out = (float*)d_out;

    dim3 g1(NE / 256, NB);
    score_kernel<<<g1, 256>>>(x);
    select_kernel<<<NB, 1024>>>(ec);
    gather_kernel<<<NB * (NC / 8) * (KSEL / 256), 256>>>(x, out);
}